// round 17
// baseline (speedup 1.0000x reference)
#include <cuda_runtime.h>
#include <cuda_pipeline.h>

// 8-point DCT-II basis as compile-time constants -> FFMA immediates after unroll.
__device__ constexpr float D8[8][8] = {
  { 0.35355339059327373f, 0.35355339059327373f, 0.35355339059327373f, 0.35355339059327373f,
    0.35355339059327373f, 0.35355339059327373f, 0.35355339059327373f, 0.35355339059327373f},
  { 0.49039264020161522f, 0.41573480615127262f, 0.27778511650980114f, 0.09754516100806417f,
   -0.09754516100806417f,-0.27778511650980114f,-0.41573480615127262f,-0.49039264020161522f},
  { 0.46193976625564337f, 0.19134171618254492f,-0.19134171618254492f,-0.46193976625564337f,
   -0.46193976625564337f,-0.19134171618254492f, 0.19134171618254492f, 0.46193976625564337f},
  { 0.41573480615127262f,-0.09754516100806417f,-0.49039264020161522f,-0.27778511650980114f,
    0.27778511650980114f, 0.49039264020161522f, 0.09754516100806417f,-0.41573480615127262f},
  { 0.35355339059327379f,-0.35355339059327379f,-0.35355339059327379f, 0.35355339059327379f,
    0.35355339059327379f,-0.35355339059327379f,-0.35355339059327379f, 0.35355339059327379f},
  { 0.27778511650980114f,-0.49039264020161522f, 0.09754516100806417f, 0.41573480615127262f,
   -0.41573480615127262f,-0.09754516100806417f, 0.49039264020161522f,-0.27778511650980114f},
  { 0.19134171618254492f,-0.46193976625564337f, 0.46193976625564337f,-0.19134171618254492f,
   -0.19134171618254492f, 0.46193976625564337f,-0.46193976625564337f, 0.19134171618254492f},
  { 0.09754516100806417f,-0.27778511650980114f, 0.41573480615127262f,-0.49039264020161522f,
    0.49039264020161522f,-0.41573480615127262f, 0.27778511650980114f,-0.09754516100806417f}
};

__constant__ float QYc[64] = {
  16,11,10,16,24,40,51,61,
  12,12,14,19,26,58,60,55,
  14,13,16,24,40,57,69,56,
  14,17,22,29,51,87,80,62,
  18,22,37,56,68,109,103,77,
  24,35,55,64,81,104,113,92,
  49,64,78,87,103,121,120,101,
  72,92,95,98,112,100,103,99
};
// Chroma table: only the 4x4 low-frequency corner is non-99.
__constant__ float QCc16[16] = {
  17,18,24,47,
  18,21,26,66,
  24,26,56,99,
  47,66,99,99
};

#define QFACTOR 0.5f
// q = 99 * QFACTOR for all chroma entries with u>=4 or v>=4.
#define QC99   49.5f
#define QC99I  0.020202020202020204f
// 1024 * D8[0][0]: DC offset equivalent of the per-pixel -128 shift.
#define DC_SHIFT 362.03867196751236f

// Forward 8-pt DCT with even/odd fold (all 8 outputs). 8 ADD + 32 FMA.
#define DCT_FWD_FOLD(in8, out8)                                            \
  {                                                                        \
    float e_[4], o_[4];                                                    \
    _Pragma("unroll")                                                      \
    for (int j_ = 0; j_ < 4; ++j_) {                                       \
      e_[j_] = in8[j_] + in8[7 - j_];                                      \
      o_[j_] = in8[j_] - in8[7 - j_];                                      \
    }                                                                      \
    _Pragma("unroll")                                                      \
    for (int v_ = 0; v_ < 8; v_ += 2) {                                    \
      float se_ = 0.f, so_ = 0.f;                                          \
      _Pragma("unroll")                                                    \
      for (int j_ = 0; j_ < 4; ++j_) {                                     \
        se_ += D8[v_][j_] * e_[j_];                                        \
        so_ += D8[v_ + 1][j_] * o_[j_];                                    \
      }                                                                    \
      out8[v_] = se_; out8[v_ + 1] = so_;                                  \
    }                                                                      \
  }

// Inverse 8-pt DCT with fold (all 8 outputs). 32 FMA + 8 ADD.
#define DCT_INV_FOLD(w8, rec8)                                             \
  {                                                                        \
    _Pragma("unroll")                                                      \
    for (int j_ = 0; j_ < 4; ++j_) {                                       \
      float E_ = 0.f, O_ = 0.f;                                            \
      _Pragma("unroll")                                                    \
      for (int v_ = 0; v_ < 8; v_ += 2) {                                  \
        E_ += D8[v_][j_] * w8[v_];                                         \
        O_ += D8[v_ + 1][j_] * w8[v_ + 1];                                 \
      }                                                                    \
      rec8[j_] = E_ + O_; rec8[7 - j_] = E_ - O_;                          \
    }                                                                      \
  }

// Tile: 32 rows x 32 cols, 256 threads, FOUR tiles per CTA, cp.async
// double-buffered pixel staging so tile i+1's loads overlap tile i's compute.
// grid 1024 CTAs = single wave at 7 CTAs/SM.
// s[blk*72 + x*9 + y]: 24 blocks (16 Y, 4 Cb, 4 Cr), conflict-free both ways.

__global__ __launch_bounds__(256, 7) void diffjpeg_kernel(
    const float* __restrict__ x, float* __restrict__ out)
{
    __shared__ float s[24 * 72];                 // 6912 B
    __shared__ float4 stage[2][3][256];          // 24576 B
    __shared__ float2 qYp[64];                   // 512 B  (q, 1/q)
    __shared__ float2 qCp16[16];                 // 128 B  (low-freq 4x4)

    const int tid = threadIdx.x;
    if (tid < 64) {
        const float a = QYc[tid] * QFACTOR;
        qYp[tid] = make_float2(a, 1.0f / a);
        if (tid < 16) {
            const float b = QCc16[tid] * QFACTOR;
            qCp16[tid] = make_float2(b, 1.0f / b);
        }
    }

    const int bz = blockIdx.z;
    const int tr = blockIdx.y;
    const size_t plane4 = 512 * 512 / 4;
    const float4* pbase = (const float4*)x + (size_t)bz * 3 * plane4 + (size_t)(tr * 32) * 128;
    float4*       obase = (float4*)out     + (size_t)bz * 3 * plane4 + (size_t)(tr * 32) * 128;

    const int row = tid >> 3;   // 0..31
    const int cg  = tid & 7;    // 0..7 -> cols 4cg..4cg+3
    const bool hi = (cg & 1);
    const int yblk = (row >> 3) * 4 + (cg >> 1);
    float* bYv = s + yblk * 72 + (row & 7) * 9;
    const size_t goff = (size_t)row * 128 + cg;

    // Prologue: stage tile 0
    {
        const float4* p0 = pbase + (blockIdx.x * 4) * 8;
        __pipeline_memcpy_async(&stage[0][0][tid], p0 + goff, 16);
        __pipeline_memcpy_async(&stage[0][1][tid], p0 + plane4 + goff, 16);
        __pipeline_memcpy_async(&stage[0][2][tid], p0 + 2 * plane4 + goff, 16);
        __pipeline_commit();
    }

    #pragma unroll 1
    for (int it = 0; it < 4; ++it) {
        const int buf = it & 1;
        float4*  po4 = obase + (blockIdx.x * 4 + it) * 8;
        if (it) __syncthreads();   // output phase of prev tile read s

        // ---- Phase 1: staged pixels -> YCbCr, Y forward-y DCT, chroma dsmp ----
        {
            __pipeline_wait_prior(0);   // this thread's copies for tile it done
            const float4 R4 = stage[buf][0][tid];
            const float4 G4 = stage[buf][1][tid];
            const float4 B4 = stage[buf][2][tid];
            // prefetch tile it+1 into the other buffer
            if (it < 3) {
                const float4* pn = pbase + (blockIdx.x * 4 + it + 1) * 8;
                __pipeline_memcpy_async(&stage[buf ^ 1][0][tid], pn + goff, 16);
                __pipeline_memcpy_async(&stage[buf ^ 1][1][tid], pn + plane4 + goff, 16);
                __pipeline_memcpy_async(&stage[buf ^ 1][2][tid], pn + 2 * plane4 + goff, 16);
                __pipeline_commit();
            }
            float rr[4] = {R4.x, R4.y, R4.z, R4.w};
            float gg[4] = {G4.x, G4.y, G4.z, G4.w};
            float bb[4] = {B4.x, B4.y, B4.z, B4.w};
            float yv[4];
            float cbh[2] = {0.f, 0.f}, crh[2] = {0.f, 0.f};
            #pragma unroll
            for (int j = 0; j < 4; ++j) {
                const float r1 = __saturatef(rr[j]);
                const float g1 = __saturatef(gg[j]);
                const float b1 = __saturatef(bb[j]);
                const float y = 76.245f * r1 + 149.685f * g1 + 29.07f * b1;
                yv[j] = y;
                cbh[j >> 1] += fmaf(b1, 255.f, -y);   // (B255 - Y)
                crh[j >> 1] += fmaf(r1, 255.f, -y);   // (R255 - Y)
            }
            float ov[4];
            #pragma unroll
            for (int j = 0; j < 4; ++j) ov[j] = __shfl_xor_sync(0xffffffffu, yv[j], 1);
            float in8[8];
            #pragma unroll
            for (int j = 0; j < 4; ++j) {
                in8[j]     = hi ? ov[j] : yv[j];
                in8[4 + j] = hi ? yv[j] : ov[j];
            }
            float out8[8];
            DCT_FWD_FOLD(in8, out8);
            out8[0] -= DC_SHIFT;   // equivalent of -128 per pixel (v=0 only)
            #pragma unroll
            for (int j = 0; j < 4; ++j)
                bYv[(hi ? 4 : 0) + j] = hi ? out8[4 + j] : out8[j];

            #pragma unroll
            for (int k = 0; k < 2; ++k) {
                cbh[k] += __shfl_xor_sync(0xffffffffu, cbh[k], 8);
                crh[k] += __shfl_xor_sync(0xffffffffu, crh[k], 8);
            }
            if ((row & 1) == 0) {
                const int crow = row >> 1;
                const int base = (crow & 7) * 9;
                #pragma unroll
                for (int k = 0; k < 2; ++k) {
                    const int ccol = 2 * cg + k;
                    const int cblk = 16 + (crow >> 3) * 2 + (ccol >> 3);
                    // 0.25 (avg) * 0.5643341 / 0.7132668 (color identity)
                    s[cblk * 72 + base + (ccol & 7)]       = 0.14108352144469527f * cbh[k];
                    s[(cblk + 4) * 72 + base + (ccol & 7)] = 0.17831669044222540f * crh[k];
                }
            }
        }
        __syncthreads();

        // ---- Region 2: Y pass-B on threads 0..127; chroma chain on 128..255 ----
        if (tid < 128) {
            const int blk = tid >> 3, v = tid & 7;
            float* bp = s + blk * 72 + v;
            float t[8];
            #pragma unroll
            for (int xx = 0; xx < 8; ++xx) t[xx] = bp[xx * 9];
            float cf[8];
            DCT_FWD_FOLD(t, cf);
            #pragma unroll
            for (int u = 0; u < 8; ++u) {
                const float2 qq = qYp[u * 8 + v];
                cf[u] = rintf(cf[u] * qq.y) * qq.x;   // round-half-even
            }
            float w[8];
            DCT_INV_FOLD(cf, w);
            #pragma unroll
            for (int xx = 0; xx < 8; ++xx) bp[xx * 9] = w[xx];
        } else {
            const int u = tid - 128;   // chroma = 8 blocks x 8 = 64 units
            if (u < 64) {
                const int blk = 16 + (u >> 3), xx = u & 7;
                float* bp = s + blk * 72 + xx * 9;
                float in8[8];
                #pragma unroll
                for (int j = 0; j < 8; ++j) in8[j] = bp[j];
                float out8[8];
                DCT_FWD_FOLD(in8, out8);
                #pragma unroll
                for (int j = 0; j < 8; ++j) bp[j] = out8[j];
            }
            asm volatile("bar.sync 1, 128;" ::: "memory");
            if (u < 64) {
                const int blk = 16 + (u >> 3), v = u & 7;
                float* bp = s + blk * 72 + v;
                float t[8];
                #pragma unroll
                for (int xx = 0; xx < 8; ++xx) t[xx] = bp[xx * 9];
                float cf[8];
                DCT_FWD_FOLD(t, cf);
                const bool in4 = (v < 4);
                #pragma unroll
                for (int uu = 0; uu < 8; ++uu) {
                    float q, inv;
                    if (uu < 4) {
                        const float2 qq = qCp16[uu * 4 + (v & 3)];
                        q   = in4 ? qq.x : QC99;
                        inv = in4 ? qq.y : QC99I;
                    } else { q = QC99; inv = QC99I; }
                    cf[uu] = rintf(cf[uu] * inv) * q;
                }
                float w[8];
                DCT_INV_FOLD(cf, w);
                #pragma unroll
                for (int xx = 0; xx < 8; ++xx) bp[xx * 9] = w[xx];
            }
            asm volatile("bar.sync 1, 128;" ::: "memory");
            if (u < 64) {
                const int blk = 16 + (u >> 3), xx = u & 7;
                float* bp = s + blk * 72 + xx * 9;
                float w[8];
                #pragma unroll
                for (int v = 0; v < 8; ++v) w[v] = bp[v];
                float rec[8];
                DCT_INV_FOLD(w, rec);
                #pragma unroll
                for (int j = 0; j < 8; ++j) bp[j] = rec[j];
            }
        }
        __syncthreads();

        // ---- Output: inverse-y for Y in registers (DC-shift restores +128)
        //      + chroma upsample + store ----
        {
            float w[8];
            #pragma unroll
            for (int v = 0; v < 8; ++v) w[v] = bYv[v];
            w[0] += DC_SHIFT;   // adds +128 to every reconstructed pixel
            float E[4], O[4];
            #pragma unroll
            for (int j = 0; j < 4; ++j) {
                float Ee = 0.f, Oo = 0.f;
                #pragma unroll
                for (int v = 0; v < 8; v += 2) {
                    Ee += D8[v][j] * w[v];
                    Oo += D8[v + 1][j] * w[v + 1];
                }
                E[j] = Ee; O[j] = Oo;
            }
            float yrec[4];
            #pragma unroll
            for (int j = 0; j < 4; ++j)
                yrec[j] = hi ? (E[3 - j] - O[3 - j]) : (E[j] + O[j]);

            const int crow = row >> 1;
            const int base = (crow & 7) * 9;
            const int ccol0 = 2 * cg;
            const int cblk = 16 + (crow >> 3) * 2 + (ccol0 >> 3);
            const float cb0 = s[cblk * 72 + base + (ccol0 & 7)];
            const float cb1 = s[cblk * 72 + base + (ccol0 & 7) + 1];
            const float cr0 = s[(cblk + 4) * 72 + base + (ccol0 & 7)];
            const float cr1 = s[(cblk + 4) * 72 + base + (ccol0 & 7) + 1];
            const float cbm[4] = {cb0, cb0, cb1, cb1};
            const float crm[4] = {cr0, cr0, cr1, cr1};
            float R[4], G[4], B[4];
            #pragma unroll
            for (int j = 0; j < 4; ++j) {
                const float yv = yrec[j];
                R[j] = __saturatef((yv + 1.402f * crm[j]) * (1.0f / 255.0f));
                G[j] = __saturatef((yv - 0.344136f * cbm[j] - 0.714136f * crm[j]) * (1.0f / 255.0f));
                B[j] = __saturatef((yv + 1.772f * cbm[j]) * (1.0f / 255.0f));
            }
            po4[goff]               = make_float4(R[0], R[1], R[2], R[3]);
            po4[plane4 + goff]      = make_float4(G[0], G[1], G[2], G[3]);
            po4[2 * plane4 + goff]  = make_float4(B[0], B[1], B[2], B[3]);
        }
    }
}

extern "C" void kernel_launch(void* const* d_in, const int* in_sizes, int n_in,
                              void* d_out, int out_size)
{
    const float* x = (const float*)d_in[0];
    float* out = (float*)d_out;
    (void)in_sizes; (void)n_in; (void)out_size;
    dim3 grid(4, 16, 16);   // tile-col quads (16/4), tile rows (512/32), batch
    diffjpeg_kernel<<<grid, 256>>>(x, out);
}